// round 15
// baseline (speedup 1.0000x reference)
#include <cuda_runtime.h>
#include <cuda_bf16.h>
#include <math.h>

#define BB 8
#define CC 256
#define NN 2048
#define HH 32
#define LDW 136
#define NT 32     // j-iterations: NT * 64 == NN

// Scratch (__device__ globals; no allocation in kernel_launch)
__device__ float    g_q [BB * NN * HH];          // q[b,n,h]   (tf32-rounded)
__device__ float    g_kT[BB * NN * HH];          // k^T[b,n,h] (tf32-rounded)
__device__ unsigned g_v [BB * CC * NN / 2];      // v[b,c,n]   bf16x2 pairs

// fused-kernel smem layout (4-byte word offsets) — i-tile 64, 2 CTAs/SM
#define OFF_Q    0                         // 64 x 36 floats (tf32)
#define OFF_KT   (64*36)                   // 2 x 64 x 36 floats
#define OFF_P    (OFF_KT + 2*64*36)        // 64 x 36 uints (bf16x2 pairs)
#define OFF_V    (OFF_P + 64*36)           // 2 x 256 x 20 uints (bf16x2 pairs)
#define OFF_RS   (OFF_V + 2*256*20)        // 64 x 4 floats
#define OFF_INV  (OFF_RS + 64*4)           // 64 floats
#define SMEM_FLOATS (OFF_INV + 64)
#define SMEM_BYTES  (SMEM_FLOATS * 4)      // 79,104 B -> 2 CTAs/SM

__device__ __forceinline__ unsigned f2tf32(float f) {
    unsigned u;
    asm("cvt.rna.tf32.f32 %0, %1;" : "=r"(u) : "f"(f));
    return u;
}

__device__ __forceinline__ unsigned pack_bf16x2(float lo, float hi) {
    unsigned u;
    asm("cvt.rn.bf16x2.f32 %0, %1, %2;" : "=r"(u) : "f"(hi), "f"(lo));
    return u;
}

__device__ __forceinline__ void mma_tf32(float c[4],
    unsigned a0, unsigned a1, unsigned a2, unsigned a3,
    unsigned b0, unsigned b1)
{
    asm volatile(
        "mma.sync.aligned.m16n8k8.row.col.f32.tf32.tf32.f32 "
        "{%0,%1,%2,%3}, {%4,%5,%6,%7}, {%8,%9}, {%0,%1,%2,%3};"
        : "+f"(c[0]), "+f"(c[1]), "+f"(c[2]), "+f"(c[3])
        : "r"(a0), "r"(a1), "r"(a2), "r"(a3), "r"(b0), "r"(b1));
}

__device__ __forceinline__ void mma_bf16(float c[4],
    unsigned a0, unsigned a1, unsigned a2, unsigned a3,
    unsigned b0, unsigned b1)
{
    asm volatile(
        "mma.sync.aligned.m16n8k16.row.col.f32.bf16.bf16.f32 "
        "{%0,%1,%2,%3}, {%4,%5,%6,%7}, {%8,%9}, {%0,%1,%2,%3};"
        : "+f"(c[0]), "+f"(c[1]), "+f"(c[2]), "+f"(c[3])
        : "r"(a0), "r"(a1), "r"(a2), "r"(a3), "r"(b0), "r"(b1));
}

__device__ __forceinline__ void cp16(unsigned dst, const void* src) {
    asm volatile("cp.async.cg.shared.global [%0], [%1], 16;\n" :: "r"(dst), "l"(src));
}
#define CP_COMMIT() asm volatile("cp.async.commit_group;\n" ::: "memory")
#define CP_WAIT(n)  asm volatile("cp.async.wait_group %0;\n" :: "n"(n) : "memory")

// ---------------------------------------------------------------------------
// Kernel 1: q/k projections, tf32x3, N-tile 128 (R12 shape — proven fastest).
// ---------------------------------------------------------------------------
__global__ __launch_bounds__(256) void qk_gemm_tf32(
    const float* __restrict__ x,
    const float* __restrict__ wq, const float* __restrict__ bq,
    const float* __restrict__ wk, const float* __restrict__ bk)
{
    const int b  = blockIdx.y;
    const int n0 = blockIdx.x * 128;
    const float* Bx = x + (size_t)b * CC * NN;

    __shared__ unsigned Ah[16][72], Al[16][72];
    __shared__ unsigned Bh[16][LDW], Bl[16][LDW];

    const int tid  = threadIdx.x;
    const int wid  = tid >> 5;
    const int lane = tid & 31;
    const int grp  = lane >> 2;
    const int qd   = lane & 3;
    const int wm   = (wid & 1) * 32;
    const int wn   = (wid >> 1) * 32;

    const int arow = tid >> 2;
    const int ak4  = (tid & 3) * 4;
    const float* asrc = (arow < 32) ? (wq + (size_t)arow * CC)
                                    : (wk + (size_t)(arow - 32) * CC);

    float acc[2][4][4];
#pragma unroll
    for (int mi = 0; mi < 2; mi++)
#pragma unroll
        for (int ni = 0; ni < 4; ni++)
#pragma unroll
            for (int r = 0; r < 4; r++) acc[mi][ni][r] = 0.f;

    float4 pa, pb[2];

    pa = *(const float4*)(asrc + ak4);
#pragma unroll
    for (int r = 0; r < 2; r++) {
        int id = tid + r * 256;
        int kb = id >> 5, nb4 = (id & 31) * 4;
        pb[r] = *(const float4*)(Bx + (size_t)kb * NN + n0 + nb4);
    }
    {
        unsigned h0 = f2tf32(pa.x), h1 = f2tf32(pa.y), h2 = f2tf32(pa.z), h3 = f2tf32(pa.w);
        Ah[ak4 + 0][arow] = h0; Al[ak4 + 0][arow] = f2tf32(pa.x - __uint_as_float(h0));
        Ah[ak4 + 1][arow] = h1; Al[ak4 + 1][arow] = f2tf32(pa.y - __uint_as_float(h1));
        Ah[ak4 + 2][arow] = h2; Al[ak4 + 2][arow] = f2tf32(pa.z - __uint_as_float(h2));
        Ah[ak4 + 3][arow] = h3; Al[ak4 + 3][arow] = f2tf32(pa.w - __uint_as_float(h3));
#pragma unroll
        for (int r = 0; r < 2; r++) {
            int id = tid + r * 256;
            int kb = id >> 5, nb4 = (id & 31) * 4;
            uint4 bh, bl;
            bh.x = f2tf32(pb[r].x); bl.x = f2tf32(pb[r].x - __uint_as_float(bh.x));
            bh.y = f2tf32(pb[r].y); bl.y = f2tf32(pb[r].y - __uint_as_float(bh.y));
            bh.z = f2tf32(pb[r].z); bl.z = f2tf32(pb[r].z - __uint_as_float(bh.z));
            bh.w = f2tf32(pb[r].w); bl.w = f2tf32(pb[r].w - __uint_as_float(bh.w));
            *(uint4*)&Bh[kb][nb4] = bh;
            *(uint4*)&Bl[kb][nb4] = bl;
        }
    }
    __syncthreads();

    for (int k0 = 0; k0 < CC; k0 += 16) {
        const bool more = (k0 + 16 < CC);
        if (more) {
            pa = *(const float4*)(asrc + k0 + 16 + ak4);
#pragma unroll
            for (int r = 0; r < 2; r++) {
                int id = tid + r * 256;
                int kb = id >> 5, nb4 = (id & 31) * 4;
                pb[r] = *(const float4*)(Bx + (size_t)(k0 + 16 + kb) * NN + n0 + nb4);
            }
        }
#pragma unroll
        for (int ka = 0; ka < 2; ka++) {
            const int k8 = ka * 8;
            unsigned ah[2][4], al[2][4], bh[4][2], bl[4][2];
#pragma unroll
            for (int mi = 0; mi < 2; mi++) {
                int mr = wm + mi * 16 + grp;
                ah[mi][0] = Ah[k8 + qd][mr];     ah[mi][1] = Ah[k8 + qd][mr + 8];
                ah[mi][2] = Ah[k8 + qd + 4][mr]; ah[mi][3] = Ah[k8 + qd + 4][mr + 8];
                al[mi][0] = Al[k8 + qd][mr];     al[mi][1] = Al[k8 + qd][mr + 8];
                al[mi][2] = Al[k8 + qd + 4][mr]; al[mi][3] = Al[k8 + qd + 4][mr + 8];
            }
#pragma unroll
            for (int ni = 0; ni < 4; ni++) {
                int nc = wn + ni * 8 + grp;
                bh[ni][0] = Bh[k8 + qd][nc]; bh[ni][1] = Bh[k8 + qd + 4][nc];
                bl[ni][0] = Bl[k8 + qd][nc]; bl[ni][1] = Bl[k8 + qd + 4][nc];
            }
#pragma unroll
            for (int mi = 0; mi < 2; mi++)
#pragma unroll
                for (int ni = 0; ni < 4; ni++) {
                    mma_tf32(acc[mi][ni], ah[mi][0], ah[mi][1], ah[mi][2], ah[mi][3],
                             bh[ni][0], bh[ni][1]);
                    mma_tf32(acc[mi][ni], ah[mi][0], ah[mi][1], ah[mi][2], ah[mi][3],
                             bl[ni][0], bl[ni][1]);
                    mma_tf32(acc[mi][ni], al[mi][0], al[mi][1], al[mi][2], al[mi][3],
                             bh[ni][0], bh[ni][1]);
                }
        }
        __syncthreads();
        if (more) {
            unsigned h0 = f2tf32(pa.x), h1 = f2tf32(pa.y), h2 = f2tf32(pa.z), h3 = f2tf32(pa.w);
            Ah[ak4 + 0][arow] = h0; Al[ak4 + 0][arow] = f2tf32(pa.x - __uint_as_float(h0));
            Ah[ak4 + 1][arow] = h1; Al[ak4 + 1][arow] = f2tf32(pa.y - __uint_as_float(h1));
            Ah[ak4 + 2][arow] = h2; Al[ak4 + 2][arow] = f2tf32(pa.z - __uint_as_float(h2));
            Ah[ak4 + 3][arow] = h3; Al[ak4 + 3][arow] = f2tf32(pa.w - __uint_as_float(h3));
#pragma unroll
            for (int r = 0; r < 2; r++) {
                int id = tid + r * 256;
                int kb = id >> 5, nb4 = (id & 31) * 4;
                uint4 bhv, blv;
                bhv.x = f2tf32(pb[r].x); blv.x = f2tf32(pb[r].x - __uint_as_float(bhv.x));
                bhv.y = f2tf32(pb[r].y); blv.y = f2tf32(pb[r].y - __uint_as_float(bhv.y));
                bhv.z = f2tf32(pb[r].z); blv.z = f2tf32(pb[r].z - __uint_as_float(bhv.z));
                bhv.w = f2tf32(pb[r].w); blv.w = f2tf32(pb[r].w - __uint_as_float(bhv.w));
                *(uint4*)&Bh[kb][nb4] = bhv;
                *(uint4*)&Bl[kb][nb4] = blv;
            }
            __syncthreads();
        }
    }

    const float* bias = (wm == 0) ? bq : bk;
    float* op = ((wm == 0) ? g_q : g_kT) + (size_t)b * NN * HH;
#pragma unroll
    for (int mi = 0; mi < 2; mi++) {
        int h0 = mi * 16 + grp;
        int h1 = h0 + 8;
        float b0 = bias[h0];
        float b1 = bias[h1];
#pragma unroll
        for (int ni = 0; ni < 4; ni++) {
            int n = n0 + wn + ni * 8 + qd * 2;
            op[(size_t)n * HH + h0]       = __uint_as_float(f2tf32(acc[mi][ni][0] + b0));
            op[(size_t)(n + 1) * HH + h0] = __uint_as_float(f2tf32(acc[mi][ni][1] + b0));
            op[(size_t)n * HH + h1]       = __uint_as_float(f2tf32(acc[mi][ni][2] + b1));
            op[(size_t)(n + 1) * HH + h1] = __uint_as_float(f2tf32(acc[mi][ni][3] + b1));
        }
    }
}

// ---------------------------------------------------------------------------
// Kernel 2: v = wv @ x + bv  (tf32 MMA); epilogue stores bf16x2 pairs.
// Unchanged from round 12.
// ---------------------------------------------------------------------------
__global__ __launch_bounds__(256) void v_gemm_tf32(
    const float* __restrict__ x, const float* __restrict__ wv,
    const float* __restrict__ bv)
{
    const int b  = blockIdx.z;
    const int m0 = blockIdx.y * 128;
    const int n0 = blockIdx.x * 128;
    const float* Bx = x + (size_t)b * CC * NN;

    __shared__ unsigned As[16][LDW];
    __shared__ unsigned Bs[16][LDW];

    const int tid  = threadIdx.x;
    const int wid  = tid >> 5;
    const int lane = tid & 31;
    const int grp  = lane >> 2;
    const int qd   = lane & 3;
    const int wm   = (wid & 1) * 64;
    const int wn   = (wid >> 1) * 32;

    float acc[4][4][4];
#pragma unroll
    for (int mi = 0; mi < 4; mi++)
#pragma unroll
        for (int ni = 0; ni < 4; ni++)
#pragma unroll
            for (int r = 0; r < 4; r++) acc[mi][ni][r] = 0.f;

    float4 pa[2], pb[2];

#pragma unroll
    for (int r = 0; r < 2; r++) {
        int ida = tid + r * 256;
        int mrow = ida >> 2, ka4 = (ida & 3) * 4;
        pa[r] = *(const float4*)(wv + (size_t)(m0 + mrow) * CC + ka4);
        int idb = tid + r * 256;
        int kb = idb >> 5, nb4 = (idb & 31) * 4;
        pb[r] = *(const float4*)(Bx + (size_t)kb * NN + n0 + nb4);
    }
#pragma unroll
    for (int r = 0; r < 2; r++) {
        int ida = tid + r * 256;
        int mrow = ida >> 2, ka4 = (ida & 3) * 4;
        As[ka4 + 0][mrow] = f2tf32(pa[r].x);
        As[ka4 + 1][mrow] = f2tf32(pa[r].y);
        As[ka4 + 2][mrow] = f2tf32(pa[r].z);
        As[ka4 + 3][mrow] = f2tf32(pa[r].w);
        int idb = tid + r * 256;
        int kb = idb >> 5, nb4 = (idb & 31) * 4;
        uint4 bb = make_uint4(f2tf32(pb[r].x), f2tf32(pb[r].y),
                              f2tf32(pb[r].z), f2tf32(pb[r].w));
        *(uint4*)&Bs[kb][nb4] = bb;
    }
    __syncthreads();

    for (int k0 = 0; k0 < CC; k0 += 16) {
        const bool more = (k0 + 16 < CC);
        if (more) {
#pragma unroll
            for (int r = 0; r < 2; r++) {
                int ida = tid + r * 256;
                int mrow = ida >> 2, ka4 = (ida & 3) * 4;
                pa[r] = *(const float4*)(wv + (size_t)(m0 + mrow) * CC + k0 + 16 + ka4);
                int idb = tid + r * 256;
                int kb = idb >> 5, nb4 = (idb & 31) * 4;
                pb[r] = *(const float4*)(Bx + (size_t)(k0 + 16 + kb) * NN + n0 + nb4);
            }
        }
#pragma unroll
        for (int ka = 0; ka < 2; ka++) {
            const int kb8 = ka * 8;
            unsigned af[4][4], bf[4][2];
#pragma unroll
            for (int mi = 0; mi < 4; mi++) {
                int mr = wm + mi * 16 + grp;
                af[mi][0] = As[kb8 + qd][mr];
                af[mi][1] = As[kb8 + qd][mr + 8];
                af[mi][2] = As[kb8 + qd + 4][mr];
                af[mi][3] = As[kb8 + qd + 4][mr + 8];
            }
#pragma unroll
            for (int ni = 0; ni < 4; ni++) {
                int nc = wn + ni * 8 + grp;
                bf[ni][0] = Bs[kb8 + qd][nc];
                bf[ni][1] = Bs[kb8 + qd + 4][nc];
            }
#pragma unroll
            for (int mi = 0; mi < 4; mi++)
#pragma unroll
                for (int ni = 0; ni < 4; ni++)
                    mma_tf32(acc[mi][ni], af[mi][0], af[mi][1], af[mi][2], af[mi][3],
                             bf[ni][0], bf[ni][1]);
        }
        __syncthreads();
        if (more) {
#pragma unroll
            for (int r = 0; r < 2; r++) {
                int ida = tid + r * 256;
                int mrow = ida >> 2, ka4 = (ida & 3) * 4;
                As[ka4 + 0][mrow] = f2tf32(pa[r].x);
                As[ka4 + 1][mrow] = f2tf32(pa[r].y);
                As[ka4 + 2][mrow] = f2tf32(pa[r].z);
                As[ka4 + 3][mrow] = f2tf32(pa[r].w);
                int idb = tid + r * 256;
                int kb = idb >> 5, nb4 = (idb & 31) * 4;
                uint4 bb = make_uint4(f2tf32(pb[r].x), f2tf32(pb[r].y),
                                      f2tf32(pb[r].z), f2tf32(pb[r].w));
                *(uint4*)&Bs[kb][nb4] = bb;
            }
            __syncthreads();
        }
    }

    // epilogue: bf16x2 pairs into g_v
#pragma unroll
    for (int mi = 0; mi < 4; mi++) {
#pragma unroll
        for (int ni = 0; ni < 4; ni++) {
            int row = m0 + wm + mi * 16 + grp;
            int col = n0 + wn + ni * 8 + qd * 2;
            float bias0 = bv[row];
            float bias1 = bv[row + 8];
            unsigned* p0 = g_v + ((size_t)b * CC + row) * (NN / 2) + col / 2;
            unsigned* p1 = p0 + (size_t)8 * (NN / 2);
            *p0 = pack_bf16x2(acc[mi][ni][0] + bias0, acc[mi][ni][1] + bias0);
            *p1 = pack_bf16x2(acc[mi][ni][2] + bias1, acc[mi][ni][3] + bias1);
        }
    }
}

// ---------------------------------------------------------------------------
// PV inner (bf16 m16n8k16, i-tile 64): D(c,i) += V(c,j)*P(i,j)^T, one 32-j half.
// Warp tile: 64 c x 32 i. V: uint pairs [256][20]; P: uint pairs [64][36].
// ---------------------------------------------------------------------------
__device__ __forceinline__ void pv_half(const float* sm, float (&pacc)[4][4][4],
                                        int cq, int iq, int grp, int qd, int h)
{
    const unsigned* Vp = (const unsigned*)(sm + OFF_V) + h * (256 * 20) + (cq * 64) * 20;
    const unsigned* Pp = (const unsigned*)(sm + OFF_P) + (iq * 32) * 36 + h * 16;
#pragma unroll
    for (int s = 0; s < 2; s++) {
        const int bp = 8 * s;
        unsigned af[4][4];
#pragma unroll
        for (int mi = 0; mi < 4; mi++) {
            af[mi][0] = Vp[(mi * 16 + grp)     * 20 + bp + qd];
            af[mi][1] = Vp[(mi * 16 + grp + 8) * 20 + bp + qd];
            af[mi][2] = Vp[(mi * 16 + grp)     * 20 + bp + qd + 4];
            af[mi][3] = Vp[(mi * 16 + grp + 8) * 20 + bp + qd + 4];
        }
        unsigned bf[4][2];
#pragma unroll
        for (int ni = 0; ni < 4; ni++) {
            bf[ni][0] = Pp[(ni * 8 + grp) * 36 + bp + qd];
            bf[ni][1] = Pp[(ni * 8 + grp) * 36 + bp + qd + 4];
        }
#pragma unroll
        for (int mi = 0; mi < 4; mi++)
#pragma unroll
            for (int ni = 0; ni < 4; ni++)
                mma_bf16(pacc[mi][ni], af[mi][0], af[mi][1], af[mi][2], af[mi][3],
                         bf[ni][0], bf[ni][1]);
    }
}

// ---------------------------------------------------------------------------
// Fused: E (tf32 x1) + exp + PV (bf16). i-tile 64, 2 CTAs/SM.
// grid (32 i-tiles, 8 batches) = 256 CTAs, 256 threads, 79.1KB smem.
// ---------------------------------------------------------------------------
__global__ __launch_bounds__(256, 2) void fused_attn(
    const float* __restrict__ x, float* __restrict__ out)
{
    extern __shared__ float sm[];
    const int b   = blockIdx.y;
    const int i0  = blockIdx.x * 64;
    const int tid = threadIdx.x;
    const int w   = tid >> 5;
    const int lane = tid & 31;
    const int grp = lane >> 2;
    const int qd  = lane & 3;

    const int ei = w & 1, ej = w >> 1;   // E warp tile: (32 i) x (16 j), ej 0..3
    const int cq = w >> 1, iq = w & 1;   // PV warp tile: (64 c) x (32 i)

    unsigned smb = (unsigned)__cvta_generic_to_shared(sm);

    const float*    gq = g_q  + ((size_t)b * NN + i0) * HH;
    const float*    gk = g_kT + (size_t)b * NN * HH;
    const unsigned* gv = g_v  + (size_t)b * CC * (NN / 2);

    // --- group A: q tile (64x32) + kT tile 0 (64x32) ---
#pragma unroll
    for (int r = 0; r < 2; r++) {
        int id = tid + 256 * r; int row = id >> 3, ch = id & 7;
        cp16(smb + (OFF_Q + row * 36 + ch * 4) * 4, gq + (size_t)row * HH + ch * 4);
    }
#pragma unroll
    for (int r = 0; r < 2; r++) {
        int id = tid + 256 * r; int row = id >> 3, ch = id & 7;
        cp16(smb + (OFF_KT + row * 36 + ch * 4) * 4, gk + (size_t)row * HH + ch * 4);
    }
    CP_COMMIT();
    // --- group B: v half0 of iter 0 (256 rows x 16 pairs) ---
#pragma unroll
    for (int r = 0; r < 4; r++) {
        int id = tid + 256 * r; int row = id >> 2, ch = id & 3;
        cp16(smb + (OFF_V + row * 20 + ch * 4) * 4, gv + (size_t)row * (NN / 2) + ch * 4);
    }
    CP_COMMIT();

    float pacc[4][4][4];
#pragma unroll
    for (int mi = 0; mi < 4; mi++)
#pragma unroll
        for (int ni = 0; ni < 4; ni++)
#pragma unroll
            for (int r = 0; r < 4; r++) pacc[mi][ni][r] = 0.f;
    float rs[4];
#pragma unroll
    for (int k = 0; k < 4; k++) rs[k] = 0.f;

    for (int it = 0; it < NT; it++) {
        const int jp0 = it * 32;       // pair offset of this iter's 64-j chunk
        const int kb = it & 1;

        // C1: v half1 of this iter -> vbuf1
#pragma unroll
        for (int r = 0; r < 4; r++) {
            int id = tid + 256 * r; int row = id >> 2, ch = id & 3;
            cp16(smb + (OFF_V + 256 * 20 + row * 20 + ch * 4) * 4,
                 gv + (size_t)row * (NN / 2) + jp0 + 16 + ch * 4);
        }
        CP_COMMIT();
        // C2: kT(it+1) -> other kT buffer
        if (it < NT - 1) {
#pragma unroll
            for (int r = 0; r < 2; r++) {
                int id = tid + 256 * r; int row = id >> 3, ch = id & 7;
                cp16(smb + (OFF_KT + (kb ^ 1) * (64 * 36) + row * 36 + ch * 4) * 4,
                     gk + (size_t)(it * 64 + 64 + row) * HH + ch * 4);
            }
        }
        CP_COMMIT();

        CP_WAIT(3); __syncthreads();   // q + kT(it) ready

        // ---------------- E phase: single tf32 (operands pre-rounded) -------
        float eacc[2][2][4];
#pragma unroll
        for (int mi = 0; mi < 2; mi++)
#pragma unroll
            for (int nj = 0; nj < 2; nj++)
#pragma unroll
                for (int r = 0; r < 4; r++) eacc[mi][nj][r] = 0.f;
        {
            const float* qs = sm + OFF_Q + ei * (32 * 36);
            const float* ks = sm + OFF_KT + kb * (64 * 36) + ej * (16 * 36);
#pragma unroll
            for (int s = 0; s < 4; s++) {
                unsigned af[2][4];
#pragma unroll
                for (int mi = 0; mi < 2; mi++) {
                    int r0 = (mi * 16 + grp)     * 36 + 8 * s + qd;
                    int r1 = (mi * 16 + grp + 8) * 36 + 8 * s + qd;
                    af[mi][0] = __float_as_uint(qs[r0]);
                    af[mi][1] = __float_as_uint(qs[r1]);
                    af[mi][2] = __float_as_uint(qs[r0 + 4]);
                    af[mi][3] = __float_as_uint(qs[r1 + 4]);
                }
                unsigned bf[2][2];
#pragma unroll
                for (int nj = 0; nj < 2; nj++) {
                    bf[nj][0] = __float_as_uint(ks[(nj * 8 + grp) * 36 + 8 * s + qd]);
                    bf[nj][1] = __float_as_uint(ks[(nj * 8 + grp) * 36 + 8 * s + qd + 4]);
                }
#pragma unroll
                for (int mi = 0; mi < 2; mi++)
#pragma unroll
                    for (int nj = 0; nj < 2; nj++)
                        mma_tf32(eacc[mi][nj], af[mi][0], af[mi][1], af[mi][2], af[mi][3],
                                 bf[nj][0], bf[nj][1]);
            }
        }
        // exp -> P (bf16x2 pairs), accumulate row sums (fp32)
        {
            unsigned* Pp = (unsigned*)(sm + OFF_P);
#pragma unroll
            for (int mi = 0; mi < 2; mi++)
#pragma unroll
                for (int nj = 0; nj < 2; nj++) {
                    float e0 = __expf(eacc[mi][nj][0]);
                    float e1 = __expf(eacc[mi][nj][1]);
                    float e2 = __expf(eacc[mi][nj][2]);
                    float e3 = __expf(eacc[mi][nj][3]);
                    rs[2 * mi]     += e0 + e1;
                    rs[2 * mi + 1] += e2 + e3;
                    int row = ei * 32 + mi * 16 + grp;
                    int pcol = ej * 8 + nj * 4 + qd;      // pair index within 32
                    Pp[row * 36 + pcol]       = pack_bf16x2(e0, e1);
                    Pp[(row + 8) * 36 + pcol] = pack_bf16x2(e2, e3);
                }
        }

        // ---------------- PV half 0 ----------------
        CP_WAIT(2); __syncthreads();   // P visible + v half0 ready
        pv_half(sm, pacc, cq, iq, grp, qd, 0);
        __syncthreads();               // all warps done with vbuf0
        // C3: v half0 of next iter -> vbuf0
        if (it < NT - 1) {
#pragma unroll
            for (int r = 0; r < 4; r++) {
                int id = tid + 256 * r; int row = id >> 2, ch = id & 3;
                cp16(smb + (OFF_V + row * 20 + ch * 4) * 4,
                     gv + (size_t)row * (NN / 2) + jp0 + 32 + ch * 4);
            }
        }
        CP_COMMIT();

        // ---------------- PV half 1 ----------------
        CP_WAIT(2); __syncthreads();   // v half1 ready
        pv_half(sm, pacc, cq, iq, grp, qd, 1);
        __syncthreads();               // vbuf1 + P free for next iter
    }

    // ---------------- rowsum reduce + inverse ----------------
#pragma unroll
    for (int k = 0; k < 4; k++) {
        rs[k] += __shfl_xor_sync(0xffffffffu, rs[k], 1);
        rs[k] += __shfl_xor_sync(0xffffffffu, rs[k], 2);
    }
    if (qd == 0) {
#pragma unroll
        for (int mi = 0; mi < 2; mi++) {
            sm[OFF_RS + (ei * 32 + mi * 16 + grp)     * 4 + ej] = rs[2 * mi];
            sm[OFF_RS + (ei * 32 + mi * 16 + grp + 8) * 4 + ej] = rs[2 * mi + 1];
        }
    }
    __syncthreads();
    if (tid < 64) {
        float t = sm[OFF_RS + tid * 4] + sm[OFF_RS + tid * 4 + 1]
                + sm[OFF_RS + tid * 4 + 2] + sm[OFF_RS + tid * 4 + 3];
        sm[OFF_INV + tid] = 1.0f / t;
    }
    __syncthreads();

    // ---------------- epilogue: out = acc/rowsum + x ----------------
#pragma unroll
    for (int mi = 0; mi < 4; mi++) {
        int c = cq * 64 + mi * 16 + grp;
        size_t rb0 = ((size_t)b * CC + c) * NN + i0;
        size_t rb1 = rb0 + (size_t)8 * NN;
#pragma unroll
        for (int ni = 0; ni < 4; ni++) {
            int il = iq * 32 + ni * 8 + 2 * qd;
            float iv0 = sm[OFF_INV + il];
            float iv1 = sm[OFF_INV + il + 1];
            float2 x0 = *(const float2*)(x + rb0 + il);
            float2 x1 = *(const float2*)(x + rb1 + il);
            float2 o0 = make_float2(pacc[mi][ni][0] * iv0 + x0.x,
                                    pacc[mi][ni][1] * iv1 + x0.y);
            float2 o1 = make_float2(pacc[mi][ni][2] * iv0 + x1.x,
                                    pacc[mi][ni][3] * iv1 + x1.y);
            *(float2*)(out + rb0 + il) = o0;
            *(float2*)(out + rb1 + il) = o1;
        }
    }
}

// ---------------------------------------------------------------------------
extern "C" void kernel_launch(void* const* d_in, const int* in_sizes, int n_in,
                              void* d_out, int out_size)
{
    const float* x  = (const float*)d_in[0];
    const float* wq = (const float*)d_in[1];
    const float* bq = (const float*)d_in[2];
    const float* wk = (const float*)d_in[3];
    const float* bk = (const float*)d_in[4];
    const float* wv = (const float*)d_in[5];
    const float* bv = (const float*)d_in[6];
    float* out = (float*)d_out;

    cudaFuncSetAttribute(fused_attn, cudaFuncAttributeMaxDynamicSharedMemorySize,
                         SMEM_BYTES);

    qk_gemm_tf32<<<dim3(NN / 128, BB), 256>>>(x, wq, bq, wk, bk);
    v_gemm_tf32<<<dim3(NN / 128, CC / 128, BB), 256>>>(x, wv, bv);
    fused_attn<<<dim3(NN / 64, BB), 256, SMEM_BYTES>>>(x, out);
}

// round 16
// speedup vs baseline: 1.2151x; 1.2151x over previous
#include <cuda_runtime.h>
#include <cuda_bf16.h>
#include <math.h>

#define BB 8
#define CC 256
#define NN 2048
#define HH 32
#define LDW 136
#define NT 32     // j-iterations: NT * 64 == NN

// Scratch (__device__ globals; no allocation in kernel_launch)
__device__ float    g_q [BB * NN * HH];          // q[b,n,h]   (tf32-rounded)
__device__ float    g_kT[BB * NN * HH];          // k^T[b,n,h] (tf32-rounded)
__device__ unsigned g_v [BB * CC * NN / 2];      // v[b,c,n]   bf16x2 pairs

// fused-kernel smem layout (4-byte word offsets) — R12 exact
#define OFF_Q    0                         // 128 x 36 floats (tf32)
#define OFF_KT   (128*36)                  // 2 x 64 x 36 floats
#define OFF_P    (OFF_KT + 2*64*36)        // 128 x 36 uints (bf16x2 pairs)
#define OFF_V    (OFF_P + 128*36)          // 2 x 256 x 20 uints (bf16x2 pairs)
#define OFF_RS   (OFF_V + 2*256*20)        // 128 x 4 floats
#define OFF_INV  (OFF_RS + 128*4)          // 128 floats
#define SMEM_FLOATS (OFF_INV + 128)
#define SMEM_BYTES  (SMEM_FLOATS * 4)      // 98,816 B

__device__ __forceinline__ unsigned f2tf32(float f) {
    unsigned u;
    asm("cvt.rna.tf32.f32 %0, %1;" : "=r"(u) : "f"(f));
    return u;
}

__device__ __forceinline__ unsigned pack_bf16x2(float lo, float hi) {
    unsigned u;
    asm("cvt.rn.bf16x2.f32 %0, %1, %2;" : "=r"(u) : "f"(hi), "f"(lo));
    return u;
}

__device__ __forceinline__ void mma_tf32(float c[4],
    unsigned a0, unsigned a1, unsigned a2, unsigned a3,
    unsigned b0, unsigned b1)
{
    asm volatile(
        "mma.sync.aligned.m16n8k8.row.col.f32.tf32.tf32.f32 "
        "{%0,%1,%2,%3}, {%4,%5,%6,%7}, {%8,%9}, {%0,%1,%2,%3};"
        : "+f"(c[0]), "+f"(c[1]), "+f"(c[2]), "+f"(c[3])
        : "r"(a0), "r"(a1), "r"(a2), "r"(a3), "r"(b0), "r"(b1));
}

__device__ __forceinline__ void mma_bf16(float c[4],
    unsigned a0, unsigned a1, unsigned a2, unsigned a3,
    unsigned b0, unsigned b1)
{
    asm volatile(
        "mma.sync.aligned.m16n8k16.row.col.f32.bf16.bf16.f32 "
        "{%0,%1,%2,%3}, {%4,%5,%6,%7}, {%8,%9}, {%0,%1,%2,%3};"
        : "+f"(c[0]), "+f"(c[1]), "+f"(c[2]), "+f"(c[3])
        : "r"(a0), "r"(a1), "r"(a2), "r"(a3), "r"(b0), "r"(b1));
}

__device__ __forceinline__ void cp16(unsigned dst, const void* src) {
    asm volatile("cp.async.cg.shared.global [%0], [%1], 16;\n" :: "r"(dst), "l"(src));
}
#define CP_COMMIT() asm volatile("cp.async.commit_group;\n" ::: "memory")
#define CP_WAIT(n)  asm volatile("cp.async.wait_group %0;\n" :: "n"(n) : "memory")

// ---------------------------------------------------------------------------
// qk body: q/k projections, tf32x3, N-tile 128 (R12 math, bit-identical).
// smem blob carve: Ah[16][72] Al[16][72] Bh[16][136] Bl[16][136]
// ---------------------------------------------------------------------------
__device__ void qk_body(unsigned* blob,
    const float* __restrict__ x,
    const float* __restrict__ wq, const float* __restrict__ bq,
    const float* __restrict__ wk, const float* __restrict__ bk,
    int nx, int b)
{
    typedef unsigned A72[72];
    typedef unsigned B136[LDW];
    A72*  Ah = (A72*) blob;
    A72*  Al = (A72*)(blob + 16 * 72);
    B136* Bh = (B136*)(blob + 32 * 72);
    B136* Bl = (B136*)(blob + 32 * 72 + 16 * LDW);

    const int n0 = nx * 128;
    const float* Bx = x + (size_t)b * CC * NN;

    const int tid  = threadIdx.x;
    const int wid  = tid >> 5;
    const int lane = tid & 31;
    const int grp  = lane >> 2;
    const int qd   = lane & 3;
    const int wm   = (wid & 1) * 32;
    const int wn   = (wid >> 1) * 32;

    const int arow = tid >> 2;
    const int ak4  = (tid & 3) * 4;
    const float* asrc = (arow < 32) ? (wq + (size_t)arow * CC)
                                    : (wk + (size_t)(arow - 32) * CC);

    float acc[2][4][4];
#pragma unroll
    for (int mi = 0; mi < 2; mi++)
#pragma unroll
        for (int ni = 0; ni < 4; ni++)
#pragma unroll
            for (int r = 0; r < 4; r++) acc[mi][ni][r] = 0.f;

    float4 pa, pb[2];

    pa = *(const float4*)(asrc + ak4);
#pragma unroll
    for (int r = 0; r < 2; r++) {
        int id = tid + r * 256;
        int kb = id >> 5, nb4 = (id & 31) * 4;
        pb[r] = *(const float4*)(Bx + (size_t)kb * NN + n0 + nb4);
    }
    {
        unsigned h0 = f2tf32(pa.x), h1 = f2tf32(pa.y), h2 = f2tf32(pa.z), h3 = f2tf32(pa.w);
        Ah[ak4 + 0][arow] = h0; Al[ak4 + 0][arow] = f2tf32(pa.x - __uint_as_float(h0));
        Ah[ak4 + 1][arow] = h1; Al[ak4 + 1][arow] = f2tf32(pa.y - __uint_as_float(h1));
        Ah[ak4 + 2][arow] = h2; Al[ak4 + 2][arow] = f2tf32(pa.z - __uint_as_float(h2));
        Ah[ak4 + 3][arow] = h3; Al[ak4 + 3][arow] = f2tf32(pa.w - __uint_as_float(h3));
#pragma unroll
        for (int r = 0; r < 2; r++) {
            int id = tid + r * 256;
            int kb = id >> 5, nb4 = (id & 31) * 4;
            uint4 bh, bl;
            bh.x = f2tf32(pb[r].x); bl.x = f2tf32(pb[r].x - __uint_as_float(bh.x));
            bh.y = f2tf32(pb[r].y); bl.y = f2tf32(pb[r].y - __uint_as_float(bh.y));
            bh.z = f2tf32(pb[r].z); bl.z = f2tf32(pb[r].z - __uint_as_float(bh.z));
            bh.w = f2tf32(pb[r].w); bl.w = f2tf32(pb[r].w - __uint_as_float(bh.w));
            *(uint4*)&Bh[kb][nb4] = bh;
            *(uint4*)&Bl[kb][nb4] = bl;
        }
    }
    __syncthreads();

    for (int k0 = 0; k0 < CC; k0 += 16) {
        const bool more = (k0 + 16 < CC);
        if (more) {
            pa = *(const float4*)(asrc + k0 + 16 + ak4);
#pragma unroll
            for (int r = 0; r < 2; r++) {
                int id = tid + r * 256;
                int kb = id >> 5, nb4 = (id & 31) * 4;
                pb[r] = *(const float4*)(Bx + (size_t)(k0 + 16 + kb) * NN + n0 + nb4);
            }
        }
#pragma unroll
        for (int ka = 0; ka < 2; ka++) {
            const int k8 = ka * 8;
            unsigned ah[2][4], al[2][4], bh[4][2], bl[4][2];
#pragma unroll
            for (int mi = 0; mi < 2; mi++) {
                int mr = wm + mi * 16 + grp;
                ah[mi][0] = Ah[k8 + qd][mr];     ah[mi][1] = Ah[k8 + qd][mr + 8];
                ah[mi][2] = Ah[k8 + qd + 4][mr]; ah[mi][3] = Ah[k8 + qd + 4][mr + 8];
                al[mi][0] = Al[k8 + qd][mr];     al[mi][1] = Al[k8 + qd][mr + 8];
                al[mi][2] = Al[k8 + qd + 4][mr]; al[mi][3] = Al[k8 + qd + 4][mr + 8];
            }
#pragma unroll
            for (int ni = 0; ni < 4; ni++) {
                int nc = wn + ni * 8 + grp;
                bh[ni][0] = Bh[k8 + qd][nc]; bh[ni][1] = Bh[k8 + qd + 4][nc];
                bl[ni][0] = Bl[k8 + qd][nc]; bl[ni][1] = Bl[k8 + qd + 4][nc];
            }
#pragma unroll
            for (int mi = 0; mi < 2; mi++)
#pragma unroll
                for (int ni = 0; ni < 4; ni++) {
                    mma_tf32(acc[mi][ni], ah[mi][0], ah[mi][1], ah[mi][2], ah[mi][3],
                             bh[ni][0], bh[ni][1]);
                    mma_tf32(acc[mi][ni], ah[mi][0], ah[mi][1], ah[mi][2], ah[mi][3],
                             bl[ni][0], bl[ni][1]);
                    mma_tf32(acc[mi][ni], al[mi][0], al[mi][1], al[mi][2], al[mi][3],
                             bh[ni][0], bh[ni][1]);
                }
        }
        __syncthreads();
        if (more) {
            unsigned h0 = f2tf32(pa.x), h1 = f2tf32(pa.y), h2 = f2tf32(pa.z), h3 = f2tf32(pa.w);
            Ah[ak4 + 0][arow] = h0; Al[ak4 + 0][arow] = f2tf32(pa.x - __uint_as_float(h0));
            Ah[ak4 + 1][arow] = h1; Al[ak4 + 1][arow] = f2tf32(pa.y - __uint_as_float(h1));
            Ah[ak4 + 2][arow] = h2; Al[ak4 + 2][arow] = f2tf32(pa.z - __uint_as_float(h2));
            Ah[ak4 + 3][arow] = h3; Al[ak4 + 3][arow] = f2tf32(pa.w - __uint_as_float(h3));
#pragma unroll
            for (int r = 0; r < 2; r++) {
                int id = tid + r * 256;
                int kb = id >> 5, nb4 = (id & 31) * 4;
                uint4 bhv, blv;
                bhv.x = f2tf32(pb[r].x); blv.x = f2tf32(pb[r].x - __uint_as_float(bhv.x));
                bhv.y = f2tf32(pb[r].y); blv.y = f2tf32(pb[r].y - __uint_as_float(bhv.y));
                bhv.z = f2tf32(pb[r].z); blv.z = f2tf32(pb[r].z - __uint_as_float(bhv.z));
                bhv.w = f2tf32(pb[r].w); blv.w = f2tf32(pb[r].w - __uint_as_float(bhv.w));
                *(uint4*)&Bh[kb][nb4] = bhv;
                *(uint4*)&Bl[kb][nb4] = blv;
            }
            __syncthreads();
        }
    }

    const float* bias = (wm == 0) ? bq : bk;
    float* op = ((wm == 0) ? g_q : g_kT) + (size_t)b * NN * HH;
#pragma unroll
    for (int mi = 0; mi < 2; mi++) {
        int h0 = mi * 16 + grp;
        int h1 = h0 + 8;
        float b0 = bias[h0];
        float b1 = bias[h1];
#pragma unroll
        for (int ni = 0; ni < 4; ni++) {
            int n = n0 + wn + ni * 8 + qd * 2;
            op[(size_t)n * HH + h0]       = __uint_as_float(f2tf32(acc[mi][ni][0] + b0));
            op[(size_t)(n + 1) * HH + h0] = __uint_as_float(f2tf32(acc[mi][ni][1] + b0));
            op[(size_t)n * HH + h1]       = __uint_as_float(f2tf32(acc[mi][ni][2] + b1));
            op[(size_t)(n + 1) * HH + h1] = __uint_as_float(f2tf32(acc[mi][ni][3] + b1));
        }
    }
}

// ---------------------------------------------------------------------------
// v body: v = wv @ x + bv (tf32, stores bf16x2) — R12 math, bit-identical.
// smem blob carve: As[16][136] Bs[16][136]
// ---------------------------------------------------------------------------
__device__ void v_body(unsigned* blob,
    const float* __restrict__ x, const float* __restrict__ wv,
    const float* __restrict__ bv, int nx, int my, int b)
{
    typedef unsigned B136[LDW];
    B136* As = (B136*) blob;
    B136* Bs = (B136*)(blob + 16 * LDW);

    const int m0 = my * 128;
    const int n0 = nx * 128;
    const float* Bx = x + (size_t)b * CC * NN;

    const int tid  = threadIdx.x;
    const int wid  = tid >> 5;
    const int lane = tid & 31;
    const int grp  = lane >> 2;
    const int qd   = lane & 3;
    const int wm   = (wid & 1) * 64;
    const int wn   = (wid >> 1) * 32;

    float acc[4][4][4];
#pragma unroll
    for (int mi = 0; mi < 4; mi++)
#pragma unroll
        for (int ni = 0; ni < 4; ni++)
#pragma unroll
            for (int r = 0; r < 4; r++) acc[mi][ni][r] = 0.f;

    float4 pa[2], pb[2];

#pragma unroll
    for (int r = 0; r < 2; r++) {
        int ida = tid + r * 256;
        int mrow = ida >> 2, ka4 = (ida & 3) * 4;
        pa[r] = *(const float4*)(wv + (size_t)(m0 + mrow) * CC + ka4);
        int idb = tid + r * 256;
        int kb = idb >> 5, nb4 = (idb & 31) * 4;
        pb[r] = *(const float4*)(Bx + (size_t)kb * NN + n0 + nb4);
    }
#pragma unroll
    for (int r = 0; r < 2; r++) {
        int ida = tid + r * 256;
        int mrow = ida >> 2, ka4 = (ida & 3) * 4;
        As[ka4 + 0][mrow] = f2tf32(pa[r].x);
        As[ka4 + 1][mrow] = f2tf32(pa[r].y);
        As[ka4 + 2][mrow] = f2tf32(pa[r].z);
        As[ka4 + 3][mrow] = f2tf32(pa[r].w);
        int idb = tid + r * 256;
        int kb = idb >> 5, nb4 = (idb & 31) * 4;
        uint4 bb = make_uint4(f2tf32(pb[r].x), f2tf32(pb[r].y),
                              f2tf32(pb[r].z), f2tf32(pb[r].w));
        *(uint4*)&Bs[kb][nb4] = bb;
    }
    __syncthreads();

    for (int k0 = 0; k0 < CC; k0 += 16) {
        const bool more = (k0 + 16 < CC);
        if (more) {
#pragma unroll
            for (int r = 0; r < 2; r++) {
                int ida = tid + r * 256;
                int mrow = ida >> 2, ka4 = (ida & 3) * 4;
                pa[r] = *(const float4*)(wv + (size_t)(m0 + mrow) * CC + k0 + 16 + ka4);
                int idb = tid + r * 256;
                int kb = idb >> 5, nb4 = (idb & 31) * 4;
                pb[r] = *(const float4*)(Bx + (size_t)(k0 + 16 + kb) * NN + n0 + nb4);
            }
        }
#pragma unroll
        for (int ka = 0; ka < 2; ka++) {
            const int kb8 = ka * 8;
            unsigned af[4][4], bf[4][2];
#pragma unroll
            for (int mi = 0; mi < 4; mi++) {
                int mr = wm + mi * 16 + grp;
                af[mi][0] = As[kb8 + qd][mr];
                af[mi][1] = As[kb8 + qd][mr + 8];
                af[mi][2] = As[kb8 + qd + 4][mr];
                af[mi][3] = As[kb8 + qd + 4][mr + 8];
            }
#pragma unroll
            for (int ni = 0; ni < 4; ni++) {
                int nc = wn + ni * 8 + grp;
                bf[ni][0] = Bs[kb8 + qd][nc];
                bf[ni][1] = Bs[kb8 + qd + 4][nc];
            }
#pragma unroll
            for (int mi = 0; mi < 4; mi++)
#pragma unroll
                for (int ni = 0; ni < 4; ni++)
                    mma_tf32(acc[mi][ni], af[mi][0], af[mi][1], af[mi][2], af[mi][3],
                             bf[ni][0], bf[ni][1]);
        }
        __syncthreads();
        if (more) {
#pragma unroll
            for (int r = 0; r < 2; r++) {
                int ida = tid + r * 256;
                int mrow = ida >> 2, ka4 = (ida & 3) * 4;
                As[ka4 + 0][mrow] = f2tf32(pa[r].x);
                As[ka4 + 1][mrow] = f2tf32(pa[r].y);
                As[ka4 + 2][mrow] = f2tf32(pa[r].z);
                As[ka4 + 3][mrow] = f2tf32(pa[r].w);
                int idb = tid + r * 256;
                int kb = idb >> 5, nb4 = (idb & 31) * 4;
                uint4 bb = make_uint4(f2tf32(pb[r].x), f2tf32(pb[r].y),
                                      f2tf32(pb[r].z), f2tf32(pb[r].w));
                *(uint4*)&Bs[kb][nb4] = bb;
            }
            __syncthreads();
        }
    }

#pragma unroll
    for (int mi = 0; mi < 4; mi++) {
#pragma unroll
        for (int ni = 0; ni < 4; ni++) {
            int row = m0 + wm + mi * 16 + grp;
            int col = n0 + wn + ni * 8 + qd * 2;
            float bias0 = bv[row];
            float bias1 = bv[row + 8];
            unsigned* p0 = g_v + ((size_t)b * CC + row) * (NN / 2) + col / 2;
            unsigned* p1 = p0 + (size_t)8 * (NN / 2);
            *p0 = pack_bf16x2(acc[mi][ni][0] + bias0, acc[mi][ni][1] + bias0);
            *p1 = pack_bf16x2(acc[mi][ni][2] + bias1, acc[mi][ni][3] + bias1);
        }
    }
}

// ---------------------------------------------------------------------------
// Combined projection kernel: blocks [0,128) -> qk, [128,384) -> v.
// ---------------------------------------------------------------------------
__global__ __launch_bounds__(256) void proj_kernel(
    const float* __restrict__ x,
    const float* __restrict__ wq, const float* __restrict__ bq,
    const float* __restrict__ wk, const float* __restrict__ bk,
    const float* __restrict__ wv, const float* __restrict__ bv)
{
    __shared__ unsigned blob[32 * 72 + 32 * LDW];   // 6656 uints = 26.6 KB

    const int bid = blockIdx.x;
    if (bid < 128) {
        qk_body(blob, x, wq, bq, wk, bk, bid & 15, bid >> 4);
    } else {
        int id = bid - 128;
        v_body(blob, x, wv, bv, id & 15, (id >> 4) & 1, id >> 5);
    }
}

// ---------------------------------------------------------------------------
// PV inner (bf16 m16n8k16): R12 exact.
// ---------------------------------------------------------------------------
__device__ __forceinline__ void pv_half(const float* sm, float (&pacc)[4][8][4],
                                        int cq, int ih, int grp, int qd, int h)
{
    const unsigned* Vp = (const unsigned*)(sm + OFF_V) + h * (256 * 20) + (cq * 64) * 20;
    const unsigned* Pp = (const unsigned*)(sm + OFF_P) + (ih * 64) * 36 + h * 16;
#pragma unroll
    for (int s = 0; s < 2; s++) {
        const int bp = 8 * s;
        unsigned af[4][4];
#pragma unroll
        for (int mi = 0; mi < 4; mi++) {
            af[mi][0] = Vp[(mi * 16 + grp)     * 20 + bp + qd];
            af[mi][1] = Vp[(mi * 16 + grp + 8) * 20 + bp + qd];
            af[mi][2] = Vp[(mi * 16 + grp)     * 20 + bp + qd + 4];
            af[mi][3] = Vp[(mi * 16 + grp + 8) * 20 + bp + qd + 4];
        }
        unsigned bf[8][2];
#pragma unroll
        for (int ni = 0; ni < 8; ni++) {
            bf[ni][0] = Pp[(ni * 8 + grp) * 36 + bp + qd];
            bf[ni][1] = Pp[(ni * 8 + grp) * 36 + bp + qd + 4];
        }
#pragma unroll
        for (int mi = 0; mi < 4; mi++)
#pragma unroll
            for (int ni = 0; ni < 8; ni++)
                mma_bf16(pacc[mi][ni], af[mi][0], af[mi][1], af[mi][2], af[mi][3],
                         bf[ni][0], bf[ni][1]);
    }
}

// ---------------------------------------------------------------------------
// Fused: E (tf32 x1) + exp + PV (bf16). R12 exact.
// grid (16 i-tiles, 8 batches), 256 threads, 98.8KB smem.
// ---------------------------------------------------------------------------
__global__ __launch_bounds__(256, 1) void fused_attn(
    const float* __restrict__ x, float* __restrict__ out)
{
    extern __shared__ float sm[];
    const int b   = blockIdx.y;
    const int i0  = blockIdx.x * 128;
    const int tid = threadIdx.x;
    const int w   = tid >> 5;
    const int lane = tid & 31;
    const int grp = lane >> 2;
    const int qd  = lane & 3;

    const int ei = w & 1, ej = w >> 1;   // E warp tile: (64 i) x (16 j)
    const int cq = w >> 1, ih = w & 1;   // PV warp tile: (64 c) x (64 i)

    unsigned smb = (unsigned)__cvta_generic_to_shared(sm);

    const float*    gq = g_q  + ((size_t)b * NN + i0) * HH;
    const float*    gk = g_kT + (size_t)b * NN * HH;
    const unsigned* gv = g_v  + (size_t)b * CC * (NN / 2);

    // --- group A: q tile (128x32) + kT tile 0 (64x32) ---
#pragma unroll
    for (int r = 0; r < 4; r++) {
        int id = tid + 256 * r; int row = id >> 3, ch = id & 7;
        cp16(smb + (OFF_Q + row * 36 + ch * 4) * 4, gq + (size_t)row * HH + ch * 4);
    }
#pragma unroll
    for (int r = 0; r < 2; r++) {
        int id = tid + 256 * r; int row = id >> 3, ch = id & 7;
        cp16(smb + (OFF_KT + row * 36 + ch * 4) * 4, gk + (size_t)row * HH + ch * 4);
    }
    CP_COMMIT();
    // --- group B: v half0 of iter 0 (256 rows x 16 pairs) ---
#pragma unroll
    for (int r = 0; r < 4; r++) {
        int id = tid + 256 * r; int row = id >> 2, ch = id & 3;
        cp16(smb + (OFF_V + row * 20 + ch * 4) * 4, gv + (size_t)row * (NN / 2) + ch * 4);
    }
    CP_COMMIT();

    float pacc[4][8][4];
#pragma unroll
    for (int mi = 0; mi < 4; mi++)
#pragma unroll
        for (int ni = 0; ni < 8; ni++)
#pragma unroll
            for (int r = 0; r < 4; r++) pacc[mi][ni][r] = 0.f;
    float rs[8];
#pragma unroll
    for (int k = 0; k < 8; k++) rs[k] = 0.f;

    for (int it = 0; it < NT; it++) {
        const int jp0 = it * 32;       // pair offset of this iter's 64-j chunk
        const int kb = it & 1;

        // C1: v half1 of this iter -> vbuf1
#pragma unroll
        for (int r = 0; r < 4; r++) {
            int id = tid + 256 * r; int row = id >> 2, ch = id & 3;
            cp16(smb + (OFF_V + 256 * 20 + row * 20 + ch * 4) * 4,
                 gv + (size_t)row * (NN / 2) + jp0 + 16 + ch * 4);
        }
        CP_COMMIT();
        // C2: kT(it+1) -> other kT buffer
        if (it < NT - 1) {
#pragma unroll
            for (int r = 0; r < 2; r++) {
                int id = tid + 256 * r; int row = id >> 3, ch = id & 7;
                cp16(smb + (OFF_KT + (kb ^ 1) * (64 * 36) + row * 36 + ch * 4) * 4,
                     gk + (size_t)(it * 64 + 64 + row) * HH + ch * 4);
            }
        }
        CP_COMMIT();

        CP_WAIT(3); __syncthreads();   // q + kT(it) ready

        // ---------------- E phase: single tf32 (operands pre-rounded) -------
        float eacc[4][2][4];
#pragma unroll
        for (int mi = 0; mi < 4; mi++)
#pragma unroll
            for (int nj = 0; nj < 2; nj++)
#pragma unroll
                for (int r = 0; r < 4; r++) eacc[mi][nj][r] = 0.f;
        {
            const float* qs = sm + OFF_Q + ei * (64 * 36);
            const float* ks = sm + OFF_KT + kb * (64 * 36) + ej * (16 * 36);
#pragma unroll
            for (int s = 0; s < 4; s++) {
                unsigned af[4][4];
#pragma unroll
                for (int mi = 0; mi < 4; mi++) {
                    int r0 = (mi * 16 + grp)     * 36 + 8 * s + qd;
                    int r1 = (mi * 16 + grp + 8) * 36 + 8 * s + qd;
                    af[mi][0] = __float_as_uint(qs[r0]);
                    af[mi][1] = __float_as_uint(qs[r1]);
                    af[mi][2] = __float_as_uint(qs[r0 + 4]);
                    af[mi][3] = __float_as_uint(qs[r1 + 4]);
                }
                unsigned bf[2][2];
#pragma unroll
                for (int nj = 0; nj < 2; nj++) {
                    bf[nj][0] = __float_as_uint(ks[(nj * 8 + grp) * 36 + 8 * s + qd]);
                    bf[nj][1] = __float_as_uint(ks[(nj * 8 + grp) * 36 + 8 * s + qd + 4]);
                }
#pragma unroll
                for (int mi = 0; mi < 4; mi++)
#pragma unroll
                    for (int nj = 0; nj < 2; nj++)
                        mma_tf32(eacc[mi][nj], af[mi][0], af[mi][1], af[mi][2], af[mi][3],
                                 bf[nj][0], bf[nj][1]);
            }
        }
        // exp -> P (bf16x2 pairs), accumulate row sums (fp32)
        {
            unsigned* Pp = (unsigned*)(sm + OFF_P);
#pragma unroll
            for (int mi = 0; mi < 4; mi++)
#pragma unroll
                for (int nj = 0; nj < 2; nj++) {
                    float e0 = __expf(eacc[mi][nj][0]);
                    float e1 = __expf(eacc[mi][nj][1]);
                    float e2 = __expf(eacc[mi][nj][2]);
                    float e3 = __expf(eacc[mi][nj][3]);
                    rs[2 * mi]     += e0 + e1;
                    rs[2 * mi + 1] += e2 + e3;
                    int row = ei * 64 + mi * 16 + grp;
                    int pcol = ej * 8 + nj * 4 + qd;      // pair index within 32
                    Pp[row * 36 + pcol]       = pack_bf16x2(e0, e1);
                    Pp[(row + 8) * 36 + pcol] = pack_bf16x2(e2, e3);
                }
        }

        // ---------------- PV half 0 ----------------
        CP_WAIT(2); __syncthreads();   // P visible + v half0 ready
        pv_half(sm, pacc, cq, ih, grp, qd, 0);
        __syncthreads();               // all warps done with vbuf0
        // C3: v half0 of next iter -> vbuf0
        if (it < NT - 1) {
#pragma unroll
            for (int r = 0; r < 4; r++) {
                int id = tid + 256 * r; int row = id >> 2, ch = id & 3;
                cp16(smb + (OFF_V + row * 20 + ch * 4) * 4,
                     gv + (size_t)row * (NN / 2) + jp0 + 32 + ch * 4);
            }
        }
        CP_COMMIT();

        // ---------------- PV half 1 ----------------
        CP_WAIT(2); __syncthreads();   // v half1 ready
        pv_half(sm, pacc, cq, ih, grp, qd, 1);
        __syncthreads();               // vbuf1 + P free for next iter
    }

    // ---------------- rowsum reduce + inverse ----------------
#pragma unroll
    for (int k = 0; k < 8; k++) {
        rs[k] += __shfl_xor_sync(0xffffffffu, rs[k], 1);
        rs[k] += __shfl_xor_sync(0xffffffffu, rs[k], 2);
    }
    if (qd == 0) {
#pragma unroll
        for (int mi = 0; mi < 4; mi++) {
            sm[OFF_RS + (ei * 64 + mi * 16 + grp)     * 4 + ej] = rs[2 * mi];
            sm[OFF_RS + (ei * 64 + mi * 16 + grp + 8) * 4 + ej] = rs[2 * mi + 1];
        }
    }
    __syncthreads();
    if (tid < 128) {
        float t = sm[OFF_RS + tid * 4] + sm[OFF_RS + tid * 4 + 1]
                + sm[OFF_RS + tid * 4 + 2] + sm[OFF_RS + tid * 4 + 3];
        sm[OFF_INV + tid] = 1.0f / t;
    }
    __syncthreads();

    // ---------------- epilogue: out = acc/rowsum + x ----------------
#pragma unroll
    for (int mi = 0; mi < 4; mi++) {
        int c = cq * 64 + mi * 16 + grp;
        size_t rb0 = ((size_t)b * CC + c) * NN + i0;
        size_t rb1 = rb0 + (size_t)8 * NN;
#pragma unroll
        for (int ni = 0; ni < 8; ni++) {
            int il = ih * 64 + ni * 8 + 2 * qd;
            float iv0 = sm[OFF_INV + il];
            float iv1 = sm[OFF_INV + il + 1];
            float2 x0 = *(const float2*)(x + rb0 + il);
            float2 x1 = *(const float2*)(x + rb1 + il);
            float2 o0 = make_float2(pacc[mi][ni][0] * iv0 + x0.x,
                                    pacc[mi][ni][1] * iv1 + x0.y);
            float2 o1 = make_float2(pacc[mi][ni][2] * iv0 + x1.x,
                                    pacc[mi][ni][3] * iv1 + x1.y);
            *(float2*)(out + rb0 + il) = o0;
            *(float2*)(out + rb1 + il) = o1;
        }
    }
}

// ---------------------------------------------------------------------------
extern "C" void kernel_launch(void* const* d_in, const int* in_sizes, int n_in,
                              void* d_out, int out_size)
{
    const float* x  = (const float*)d_in[0];
    const float* wq = (const float*)d_in[1];
    const float* bq = (const float*)d_in[2];
    const float* wk = (const float*)d_in[3];
    const float* bk = (const float*)d_in[4];
    const float* wv = (const float*)d_in[5];
    const float* bv = (const float*)d_in[6];
    float* out = (float*)d_out;

    cudaFuncSetAttribute(fused_attn, cudaFuncAttributeMaxDynamicSharedMemorySize,
                         SMEM_BYTES);

    proj_kernel<<<384, 256>>>(x, wq, bq, wk, bk, wv, bv);
    fused_attn<<<dim3(NN / 128, BB), 256, SMEM_BYTES>>>(x, out);
}

// round 17
// speedup vs baseline: 1.3029x; 1.0723x over previous
#include <cuda_runtime.h>
#include <cuda_bf16.h>
#include <math.h>

#define BB 8
#define CC 256
#define NN 2048
#define HH 32
#define LDW 136
#define NT 32     // j-iterations: NT * 64 == NN

// Scratch (__device__ globals; no allocation in kernel_launch)
__device__ float    g_q [BB * NN * HH];          // q[b,n,h]   (tf32-rounded)
__device__ float    g_kT[BB * NN * HH];          // k^T[b,n,h] (tf32-rounded)
__device__ unsigned g_v [BB * CC * NN / 2];      // v[b,c,n]   bf16x2 pairs

// fused-kernel smem layout (4-byte word offsets) — P double-buffered
#define OFF_Q    0                         // 128 x 36 floats (tf32)
#define OFF_KT   (128*36)                  // 2 x 64 x 36 floats
#define OFF_P    (OFF_KT + 2*64*36)        // 2 x 128 x 36 uints (bf16x2 pairs)
#define OFF_V    (OFF_P + 2*128*36)        // 2 x 256 x 20 uints (bf16x2 pairs)
#define OFF_RS   (OFF_V + 2*256*20)        // 128 x 4 floats
#define OFF_INV  (OFF_RS + 128*4)          // 128 floats
#define SMEM_FLOATS (OFF_INV + 128)
#define SMEM_BYTES  (SMEM_FLOATS * 4)      // 117,248 B

__device__ __forceinline__ unsigned f2tf32(float f) {
    unsigned u;
    asm("cvt.rna.tf32.f32 %0, %1;" : "=r"(u) : "f"(f));
    return u;
}

__device__ __forceinline__ unsigned pack_bf16x2(float lo, float hi) {
    unsigned u;
    asm("cvt.rn.bf16x2.f32 %0, %1, %2;" : "=r"(u) : "f"(hi), "f"(lo));
    return u;
}

__device__ __forceinline__ void mma_tf32(float c[4],
    unsigned a0, unsigned a1, unsigned a2, unsigned a3,
    unsigned b0, unsigned b1)
{
    asm volatile(
        "mma.sync.aligned.m16n8k8.row.col.f32.tf32.tf32.f32 "
        "{%0,%1,%2,%3}, {%4,%5,%6,%7}, {%8,%9}, {%0,%1,%2,%3};"
        : "+f"(c[0]), "+f"(c[1]), "+f"(c[2]), "+f"(c[3])
        : "r"(a0), "r"(a1), "r"(a2), "r"(a3), "r"(b0), "r"(b1));
}

__device__ __forceinline__ void mma_bf16(float c[4],
    unsigned a0, unsigned a1, unsigned a2, unsigned a3,
    unsigned b0, unsigned b1)
{
    asm volatile(
        "mma.sync.aligned.m16n8k16.row.col.f32.bf16.bf16.f32 "
        "{%0,%1,%2,%3}, {%4,%5,%6,%7}, {%8,%9}, {%0,%1,%2,%3};"
        : "+f"(c[0]), "+f"(c[1]), "+f"(c[2]), "+f"(c[3])
        : "r"(a0), "r"(a1), "r"(a2), "r"(a3), "r"(b0), "r"(b1));
}

__device__ __forceinline__ void cp16(unsigned dst, const void* src) {
    asm volatile("cp.async.cg.shared.global [%0], [%1], 16;\n" :: "r"(dst), "l"(src));
}
#define CP_COMMIT() asm volatile("cp.async.commit_group;\n" ::: "memory")
#define CP_WAIT(n)  asm volatile("cp.async.wait_group %0;\n" :: "n"(n) : "memory")

// ---------------------------------------------------------------------------
// qk body: q/k projections, tf32x3, N-tile 128 (R12 math, bit-identical).
// ---------------------------------------------------------------------------
__device__ void qk_body(unsigned* blob,
    const float* __restrict__ x,
    const float* __restrict__ wq, const float* __restrict__ bq,
    const float* __restrict__ wk, const float* __restrict__ bk,
    int nx, int b)
{
    typedef unsigned A72[72];
    typedef unsigned B136[LDW];
    A72*  Ah = (A72*) blob;
    A72*  Al = (A72*)(blob + 16 * 72);
    B136* Bh = (B136*)(blob + 32 * 72);
    B136* Bl = (B136*)(blob + 32 * 72 + 16 * LDW);

    const int n0 = nx * 128;
    const float* Bx = x + (size_t)b * CC * NN;

    const int tid  = threadIdx.x;
    const int wid  = tid >> 5;
    const int lane = tid & 31;
    const int grp  = lane >> 2;
    const int qd   = lane & 3;
    const int wm   = (wid & 1) * 32;
    const int wn   = (wid >> 1) * 32;

    const int arow = tid >> 2;
    const int ak4  = (tid & 3) * 4;
    const float* asrc = (arow < 32) ? (wq + (size_t)arow * CC)
                                    : (wk + (size_t)(arow - 32) * CC);

    float acc[2][4][4];
#pragma unroll
    for (int mi = 0; mi < 2; mi++)
#pragma unroll
        for (int ni = 0; ni < 4; ni++)
#pragma unroll
            for (int r = 0; r < 4; r++) acc[mi][ni][r] = 0.f;

    float4 pa, pb[2];

    pa = *(const float4*)(asrc + ak4);
#pragma unroll
    for (int r = 0; r < 2; r++) {
        int id = tid + r * 256;
        int kb = id >> 5, nb4 = (id & 31) * 4;
        pb[r] = *(const float4*)(Bx + (size_t)kb * NN + n0 + nb4);
    }
    {
        unsigned h0 = f2tf32(pa.x), h1 = f2tf32(pa.y), h2 = f2tf32(pa.z), h3 = f2tf32(pa.w);
        Ah[ak4 + 0][arow] = h0; Al[ak4 + 0][arow] = f2tf32(pa.x - __uint_as_float(h0));
        Ah[ak4 + 1][arow] = h1; Al[ak4 + 1][arow] = f2tf32(pa.y - __uint_as_float(h1));
        Ah[ak4 + 2][arow] = h2; Al[ak4 + 2][arow] = f2tf32(pa.z - __uint_as_float(h2));
        Ah[ak4 + 3][arow] = h3; Al[ak4 + 3][arow] = f2tf32(pa.w - __uint_as_float(h3));
#pragma unroll
        for (int r = 0; r < 2; r++) {
            int id = tid + r * 256;
            int kb = id >> 5, nb4 = (id & 31) * 4;
            uint4 bh, bl;
            bh.x = f2tf32(pb[r].x); bl.x = f2tf32(pb[r].x - __uint_as_float(bh.x));
            bh.y = f2tf32(pb[r].y); bl.y = f2tf32(pb[r].y - __uint_as_float(bh.y));
            bh.z = f2tf32(pb[r].z); bl.z = f2tf32(pb[r].z - __uint_as_float(bh.z));
            bh.w = f2tf32(pb[r].w); bl.w = f2tf32(pb[r].w - __uint_as_float(bh.w));
            *(uint4*)&Bh[kb][nb4] = bh;
            *(uint4*)&Bl[kb][nb4] = bl;
        }
    }
    __syncthreads();

    for (int k0 = 0; k0 < CC; k0 += 16) {
        const bool more = (k0 + 16 < CC);
        if (more) {
            pa = *(const float4*)(asrc + k0 + 16 + ak4);
#pragma unroll
            for (int r = 0; r < 2; r++) {
                int id = tid + r * 256;
                int kb = id >> 5, nb4 = (id & 31) * 4;
                pb[r] = *(const float4*)(Bx + (size_t)(k0 + 16 + kb) * NN + n0 + nb4);
            }
        }
#pragma unroll
        for (int ka = 0; ka < 2; ka++) {
            const int k8 = ka * 8;
            unsigned ah[2][4], al[2][4], bh[4][2], bl[4][2];
#pragma unroll
            for (int mi = 0; mi < 2; mi++) {
                int mr = wm + mi * 16 + grp;
                ah[mi][0] = Ah[k8 + qd][mr];     ah[mi][1] = Ah[k8 + qd][mr + 8];
                ah[mi][2] = Ah[k8 + qd + 4][mr]; ah[mi][3] = Ah[k8 + qd + 4][mr + 8];
                al[mi][0] = Al[k8 + qd][mr];     al[mi][1] = Al[k8 + qd][mr + 8];
                al[mi][2] = Al[k8 + qd + 4][mr]; al[mi][3] = Al[k8 + qd + 4][mr + 8];
            }
#pragma unroll
            for (int ni = 0; ni < 4; ni++) {
                int nc = wn + ni * 8 + grp;
                bh[ni][0] = Bh[k8 + qd][nc]; bh[ni][1] = Bh[k8 + qd + 4][nc];
                bl[ni][0] = Bl[k8 + qd][nc]; bl[ni][1] = Bl[k8 + qd + 4][nc];
            }
#pragma unroll
            for (int mi = 0; mi < 2; mi++)
#pragma unroll
                for (int ni = 0; ni < 4; ni++) {
                    mma_tf32(acc[mi][ni], ah[mi][0], ah[mi][1], ah[mi][2], ah[mi][3],
                             bh[ni][0], bh[ni][1]);
                    mma_tf32(acc[mi][ni], ah[mi][0], ah[mi][1], ah[mi][2], ah[mi][3],
                             bl[ni][0], bl[ni][1]);
                    mma_tf32(acc[mi][ni], al[mi][0], al[mi][1], al[mi][2], al[mi][3],
                             bh[ni][0], bh[ni][1]);
                }
        }
        __syncthreads();
        if (more) {
            unsigned h0 = f2tf32(pa.x), h1 = f2tf32(pa.y), h2 = f2tf32(pa.z), h3 = f2tf32(pa.w);
            Ah[ak4 + 0][arow] = h0; Al[ak4 + 0][arow] = f2tf32(pa.x - __uint_as_float(h0));
            Ah[ak4 + 1][arow] = h1; Al[ak4 + 1][arow] = f2tf32(pa.y - __uint_as_float(h1));
            Ah[ak4 + 2][arow] = h2; Al[ak4 + 2][arow] = f2tf32(pa.z - __uint_as_float(h2));
            Ah[ak4 + 3][arow] = h3; Al[ak4 + 3][arow] = f2tf32(pa.w - __uint_as_float(h3));
#pragma unroll
            for (int r = 0; r < 2; r++) {
                int id = tid + r * 256;
                int kb = id >> 5, nb4 = (id & 31) * 4;
                uint4 bhv, blv;
                bhv.x = f2tf32(pb[r].x); blv.x = f2tf32(pb[r].x - __uint_as_float(bhv.x));
                bhv.y = f2tf32(pb[r].y); blv.y = f2tf32(pb[r].y - __uint_as_float(bhv.y));
                bhv.z = f2tf32(pb[r].z); blv.z = f2tf32(pb[r].z - __uint_as_float(bhv.z));
                bhv.w = f2tf32(pb[r].w); blv.w = f2tf32(pb[r].w - __uint_as_float(bhv.w));
                *(uint4*)&Bh[kb][nb4] = bhv;
                *(uint4*)&Bl[kb][nb4] = blv;
            }
            __syncthreads();
        }
    }

    const float* bias = (wm == 0) ? bq : bk;
    float* op = ((wm == 0) ? g_q : g_kT) + (size_t)b * NN * HH;
#pragma unroll
    for (int mi = 0; mi < 2; mi++) {
        int h0 = mi * 16 + grp;
        int h1 = h0 + 8;
        float b0 = bias[h0];
        float b1 = bias[h1];
#pragma unroll
        for (int ni = 0; ni < 4; ni++) {
            int n = n0 + wn + ni * 8 + qd * 2;
            op[(size_t)n * HH + h0]       = __uint_as_float(f2tf32(acc[mi][ni][0] + b0));
            op[(size_t)(n + 1) * HH + h0] = __uint_as_float(f2tf32(acc[mi][ni][1] + b0));
            op[(size_t)n * HH + h1]       = __uint_as_float(f2tf32(acc[mi][ni][2] + b1));
            op[(size_t)(n + 1) * HH + h1] = __uint_as_float(f2tf32(acc[mi][ni][3] + b1));
        }
    }
}

// ---------------------------------------------------------------------------
// v body: v = wv @ x + bv (tf32, stores bf16x2) — R12 math, bit-identical.
// ---------------------------------------------------------------------------
__device__ void v_body(unsigned* blob,
    const float* __restrict__ x, const float* __restrict__ wv,
    const float* __restrict__ bv, int nx, int my, int b)
{
    typedef unsigned B136[LDW];
    B136* As = (B136*) blob;
    B136* Bs = (B136*)(blob + 16 * LDW);

    const int m0 = my * 128;
    const int n0 = nx * 128;
    const float* Bx = x + (size_t)b * CC * NN;

    const int tid  = threadIdx.x;
    const int wid  = tid >> 5;
    const int lane = tid & 31;
    const int grp  = lane >> 2;
    const int qd   = lane & 3;
    const int wm   = (wid & 1) * 64;
    const int wn   = (wid >> 1) * 32;

    float acc[4][4][4];
#pragma unroll
    for (int mi = 0; mi < 4; mi++)
#pragma unroll
        for (int ni = 0; ni < 4; ni++)
#pragma unroll
            for (int r = 0; r < 4; r++) acc[mi][ni][r] = 0.f;

    float4 pa[2], pb[2];

#pragma unroll
    for (int r = 0; r < 2; r++) {
        int ida = tid + r * 256;
        int mrow = ida >> 2, ka4 = (ida & 3) * 4;
        pa[r] = *(const float4*)(wv + (size_t)(m0 + mrow) * CC + ka4);
        int idb = tid + r * 256;
        int kb = idb >> 5, nb4 = (idb & 31) * 4;
        pb[r] = *(const float4*)(Bx + (size_t)kb * NN + n0 + nb4);
    }
#pragma unroll
    for (int r = 0; r < 2; r++) {
        int ida = tid + r * 256;
        int mrow = ida >> 2, ka4 = (ida & 3) * 4;
        As[ka4 + 0][mrow] = f2tf32(pa[r].x);
        As[ka4 + 1][mrow] = f2tf32(pa[r].y);
        As[ka4 + 2][mrow] = f2tf32(pa[r].z);
        As[ka4 + 3][mrow] = f2tf32(pa[r].w);
        int idb = tid + r * 256;
        int kb = idb >> 5, nb4 = (idb & 31) * 4;
        uint4 bb = make_uint4(f2tf32(pb[r].x), f2tf32(pb[r].y),
                              f2tf32(pb[r].z), f2tf32(pb[r].w));
        *(uint4*)&Bs[kb][nb4] = bb;
    }
    __syncthreads();

    for (int k0 = 0; k0 < CC; k0 += 16) {
        const bool more = (k0 + 16 < CC);
        if (more) {
#pragma unroll
            for (int r = 0; r < 2; r++) {
                int ida = tid + r * 256;
                int mrow = ida >> 2, ka4 = (ida & 3) * 4;
                pa[r] = *(const float4*)(wv + (size_t)(m0 + mrow) * CC + k0 + 16 + ka4);
                int idb = tid + r * 256;
                int kb = idb >> 5, nb4 = (idb & 31) * 4;
                pb[r] = *(const float4*)(Bx + (size_t)(k0 + 16 + kb) * NN + n0 + nb4);
            }
        }
#pragma unroll
        for (int ka = 0; ka < 2; ka++) {
            const int kb8 = ka * 8;
            unsigned af[4][4], bf[4][2];
#pragma unroll
            for (int mi = 0; mi < 4; mi++) {
                int mr = wm + mi * 16 + grp;
                af[mi][0] = As[kb8 + qd][mr];
                af[mi][1] = As[kb8 + qd][mr + 8];
                af[mi][2] = As[kb8 + qd + 4][mr];
                af[mi][3] = As[kb8 + qd + 4][mr + 8];
            }
#pragma unroll
            for (int ni = 0; ni < 4; ni++) {
                int nc = wn + ni * 8 + grp;
                bf[ni][0] = Bs[kb8 + qd][nc];
                bf[ni][1] = Bs[kb8 + qd + 4][nc];
            }
#pragma unroll
            for (int mi = 0; mi < 4; mi++)
#pragma unroll
                for (int ni = 0; ni < 4; ni++)
                    mma_tf32(acc[mi][ni], af[mi][0], af[mi][1], af[mi][2], af[mi][3],
                             bf[ni][0], bf[ni][1]);
        }
        __syncthreads();
        if (more) {
#pragma unroll
            for (int r = 0; r < 2; r++) {
                int ida = tid + r * 256;
                int mrow = ida >> 2, ka4 = (ida & 3) * 4;
                As[ka4 + 0][mrow] = f2tf32(pa[r].x);
                As[ka4 + 1][mrow] = f2tf32(pa[r].y);
                As[ka4 + 2][mrow] = f2tf32(pa[r].z);
                As[ka4 + 3][mrow] = f2tf32(pa[r].w);
                int idb = tid + r * 256;
                int kb = idb >> 5, nb4 = (idb & 31) * 4;
                uint4 bb = make_uint4(f2tf32(pb[r].x), f2tf32(pb[r].y),
                                      f2tf32(pb[r].z), f2tf32(pb[r].w));
                *(uint4*)&Bs[kb][nb4] = bb;
            }
            __syncthreads();
        }
    }

#pragma unroll
    for (int mi = 0; mi < 4; mi++) {
#pragma unroll
        for (int ni = 0; ni < 4; ni++) {
            int row = m0 + wm + mi * 16 + grp;
            int col = n0 + wn + ni * 8 + qd * 2;
            float bias0 = bv[row];
            float bias1 = bv[row + 8];
            unsigned* p0 = g_v + ((size_t)b * CC + row) * (NN / 2) + col / 2;
            unsigned* p1 = p0 + (size_t)8 * (NN / 2);
            *p0 = pack_bf16x2(acc[mi][ni][0] + bias0, acc[mi][ni][1] + bias0);
            *p1 = pack_bf16x2(acc[mi][ni][2] + bias1, acc[mi][ni][3] + bias1);
        }
    }
}

// ---------------------------------------------------------------------------
// Combined projection kernel: blocks [0,128) -> qk, [128,384) -> v.
// ---------------------------------------------------------------------------
__global__ __launch_bounds__(256) void proj_kernel(
    const float* __restrict__ x,
    const float* __restrict__ wq, const float* __restrict__ bq,
    const float* __restrict__ wk, const float* __restrict__ bk,
    const float* __restrict__ wv, const float* __restrict__ bv)
{
    __shared__ unsigned blob[32 * 72 + 32 * LDW];   // 26.6 KB

    const int bid = blockIdx.x;
    if (bid < 128) {
        qk_body(blob, x, wq, bq, wk, bk, bid & 15, bid >> 4);
    } else {
        int id = bid - 128;
        v_body(blob, x, wv, bv, id & 15, (id >> 4) & 1, id >> 5);
    }
}

// ---------------------------------------------------------------------------
// PV inner (bf16 m16n8k16): one 32-j half, selectable P buffer.
// ---------------------------------------------------------------------------
__device__ __forceinline__ void pv_half(const float* sm, float (&pacc)[4][8][4],
                                        int cq, int ih, int grp, int qd,
                                        int h, int pbuf)
{
    const unsigned* Vp = (const unsigned*)(sm + OFF_V) + h * (256 * 20) + (cq * 64) * 20;
    const unsigned* Pp = (const unsigned*)(sm + OFF_P) + pbuf * (128 * 36)
                         + (ih * 64) * 36 + h * 16;
#pragma unroll
    for (int s = 0; s < 2; s++) {
        const int bp = 8 * s;
        unsigned af[4][4];
#pragma unroll
        for (int mi = 0; mi < 4; mi++) {
            af[mi][0] = Vp[(mi * 16 + grp)     * 20 + bp + qd];
            af[mi][1] = Vp[(mi * 16 + grp + 8) * 20 + bp + qd];
            af[mi][2] = Vp[(mi * 16 + grp)     * 20 + bp + qd + 4];
            af[mi][3] = Vp[(mi * 16 + grp + 8) * 20 + bp + qd + 4];
        }
        unsigned bf[8][2];
#pragma unroll
        for (int ni = 0; ni < 8; ni++) {
            bf[ni][0] = Pp[(ni * 8 + grp) * 36 + bp + qd];
            bf[ni][1] = Pp[(ni * 8 + grp) * 36 + bp + qd + 4];
        }
#pragma unroll
        for (int mi = 0; mi < 4; mi++)
#pragma unroll
            for (int ni = 0; ni < 8; ni++)
                mma_bf16(pacc[mi][ni], af[mi][0], af[mi][1], af[mi][2], af[mi][3],
                         bf[ni][0], bf[ni][1]);
    }
}

// ---------------------------------------------------------------------------
// E phase: single tf32 (operands pre-rounded) into eacc.
// ---------------------------------------------------------------------------
__device__ __forceinline__ void e_phase(const float* sm, float (&eacc)[4][2][4],
                                        int kb, int ei, int ej, int grp, int qd)
{
#pragma unroll
    for (int mi = 0; mi < 4; mi++)
#pragma unroll
        for (int nj = 0; nj < 2; nj++)
#pragma unroll
            for (int r = 0; r < 4; r++) eacc[mi][nj][r] = 0.f;
    const float* qs = sm + OFF_Q + ei * (64 * 36);
    const float* ks = sm + OFF_KT + kb * (64 * 36) + ej * (16 * 36);
#pragma unroll
    for (int s = 0; s < 4; s++) {
        unsigned af[4][4];
#pragma unroll
        for (int mi = 0; mi < 4; mi++) {
            int r0 = (mi * 16 + grp)     * 36 + 8 * s + qd;
            int r1 = (mi * 16 + grp + 8) * 36 + 8 * s + qd;
            af[mi][0] = __float_as_uint(qs[r0]);
            af[mi][1] = __float_as_uint(qs[r1]);
            af[mi][2] = __float_as_uint(qs[r0 + 4]);
            af[mi][3] = __float_as_uint(qs[r1 + 4]);
        }
        unsigned bf[2][2];
#pragma unroll
        for (int nj = 0; nj < 2; nj++) {
            bf[nj][0] = __float_as_uint(ks[(nj * 8 + grp) * 36 + 8 * s + qd]);
            bf[nj][1] = __float_as_uint(ks[(nj * 8 + grp) * 36 + 8 * s + qd + 4]);
        }
#pragma unroll
        for (int mi = 0; mi < 4; mi++)
#pragma unroll
            for (int nj = 0; nj < 2; nj++)
                mma_tf32(eacc[mi][nj], af[mi][0], af[mi][1], af[mi][2], af[mi][3],
                         bf[nj][0], bf[nj][1]);
    }
}

// ---------------------------------------------------------------------------
// exp -> P[pbuf] (bf16x2 pairs), accumulate row sums.
// ---------------------------------------------------------------------------
__device__ __forceinline__ void exp_store(float* sm, float (&eacc)[4][2][4],
                                          float (&rs)[8], int pbuf,
                                          int ei, int ej, int grp, int qd)
{
    unsigned* Pp = (unsigned*)(sm + OFF_P) + pbuf * (128 * 36);
#pragma unroll
    for (int mi = 0; mi < 4; mi++)
#pragma unroll
        for (int nj = 0; nj < 2; nj++) {
            float e0 = __expf(eacc[mi][nj][0]);
            float e1 = __expf(eacc[mi][nj][1]);
            float e2 = __expf(eacc[mi][nj][2]);
            float e3 = __expf(eacc[mi][nj][3]);
            rs[2 * mi]     += e0 + e1;
            rs[2 * mi + 1] += e2 + e3;
            int row = ei * 64 + mi * 16 + grp;
            int pcol = ej * 8 + nj * 4 + qd;
            Pp[row * 36 + pcol]       = pack_bf16x2(e0, e1);
            Pp[(row + 8) * 36 + pcol] = pack_bf16x2(e2, e3);
        }
}

// ---------------------------------------------------------------------------
// Fused: software-pipelined E/PV. PV(it-1)h1 executes inside iter it, back-to-
// back with E(it)'s independent MMAs so they fill each other's latency.
// grid (16 i-tiles, 8 batches), 256 threads, 117.2KB smem, 4 barriers/iter.
// ---------------------------------------------------------------------------
__global__ __launch_bounds__(256, 1) void fused_attn(
    const float* __restrict__ x, float* __restrict__ out)
{
    extern __shared__ float sm[];
    const int b   = blockIdx.y;
    const int i0  = blockIdx.x * 128;
    const int tid = threadIdx.x;
    const int w   = tid >> 5;
    const int lane = tid & 31;
    const int grp = lane >> 2;
    const int qd  = lane & 3;

    const int ei = w & 1, ej = w >> 1;   // E warp tile: (64 i) x (16 j)
    const int cq = w >> 1, ih = w & 1;   // PV warp tile: (64 c) x (64 i)

    unsigned smb = (unsigned)__cvta_generic_to_shared(sm);

    const float*    gq = g_q  + ((size_t)b * NN + i0) * HH;
    const float*    gk = g_kT + (size_t)b * NN * HH;
    const unsigned* gv = g_v  + (size_t)b * CC * (NN / 2);

    // --- G1: q tile + kT(0) ---
#pragma unroll
    for (int r = 0; r < 4; r++) {
        int id = tid + 256 * r; int row = id >> 3, ch = id & 7;
        cp16(smb + (OFF_Q + row * 36 + ch * 4) * 4, gq + (size_t)row * HH + ch * 4);
    }
#pragma unroll
    for (int r = 0; r < 2; r++) {
        int id = tid + 256 * r; int row = id >> 3, ch = id & 7;
        cp16(smb + (OFF_KT + row * 36 + ch * 4) * 4, gk + (size_t)row * HH + ch * 4);
    }
    CP_COMMIT();
    // --- G2: empty (keeps group counts uniform) ---
    CP_COMMIT();
    // --- G3: V(0)h0 ---
#pragma unroll
    for (int r = 0; r < 4; r++) {
        int id = tid + 256 * r; int row = id >> 2, ch = id & 3;
        cp16(smb + (OFF_V + row * 20 + ch * 4) * 4, gv + (size_t)row * (NN / 2) + ch * 4);
    }
    CP_COMMIT();

    float pacc[4][8][4];
#pragma unroll
    for (int mi = 0; mi < 4; mi++)
#pragma unroll
        for (int ni = 0; ni < 8; ni++)
#pragma unroll
            for (int r = 0; r < 4; r++) pacc[mi][ni][r] = 0.f;
    float rs[8];
#pragma unroll
    for (int k = 0; k < 8; k++) rs[k] = 0.f;

    float eacc[4][2][4];

    // ================= iteration 0 (peeled: no PV h1 yet) =================
    {
        CP_WAIT(1); __syncthreads();           // Q + kT(0) ready
        e_phase(sm, eacc, 0, ei, ej, grp, qd);
        exp_store(sm, eacc, rs, 0, ei, ej, grp, qd);
        __syncthreads();                       // P[0] visible
        // C1: V(0)h1
#pragma unroll
        for (int r = 0; r < 4; r++) {
            int id = tid + 256 * r; int row = id >> 2, ch = id & 3;
            cp16(smb + (OFF_V + 256 * 20 + row * 20 + ch * 4) * 4,
                 gv + (size_t)row * (NN / 2) + 16 + ch * 4);
        }
        CP_COMMIT();
        // C2: kT(1)
#pragma unroll
        for (int r = 0; r < 2; r++) {
            int id = tid + 256 * r; int row = id >> 3, ch = id & 7;
            cp16(smb + (OFF_KT + (64 * 36) + row * 36 + ch * 4) * 4,
                 gk + (size_t)(64 + row) * HH + ch * 4);
        }
        CP_COMMIT();
        CP_WAIT(2); __syncthreads();           // V(0)h0 ready
        pv_half(sm, pacc, cq, ih, grp, qd, 0, 0);
        __syncthreads();                       // vh0 free
        // C3: V(1)h0
#pragma unroll
        for (int r = 0; r < 4; r++) {
            int id = tid + 256 * r; int row = id >> 2, ch = id & 3;
            cp16(smb + (OFF_V + row * 20 + ch * 4) * 4,
                 gv + (size_t)row * (NN / 2) + 32 + ch * 4);
        }
        CP_COMMIT();
    }

    // ================= main loop it = 1..NT-1 =================
    for (int it = 1; it < NT; it++) {
        const int jp0 = it * 32;
        const int kb = it & 1;
        const int pp = it & 1;

        CP_WAIT(1); __syncthreads();           // kT(it) + V(it-1)h1 ready

        // E(it) MMAs and PV(it-1)h1 MMAs are independent; same basic block so
        // the scheduler interleaves them (and PV fills the exp MUFU window).
        e_phase(sm, eacc, kb, ei, ej, grp, qd);
        pv_half(sm, pacc, cq, ih, grp, qd, 1, pp ^ 1);
        exp_store(sm, eacc, rs, pp, ei, ej, grp, qd);

        __syncthreads();                       // P[pp] visible; vh1 readers done

        // C1: V(it)h1 -> vh1
#pragma unroll
        for (int r = 0; r < 4; r++) {
            int id = tid + 256 * r; int row = id >> 2, ch = id & 3;
            cp16(smb + (OFF_V + 256 * 20 + row * 20 + ch * 4) * 4,
                 gv + (size_t)row * (NN / 2) + jp0 + 16 + ch * 4);
        }
        CP_COMMIT();
        // C2: kT(it+1) -> other kT buffer
        if (it < NT - 1) {
#pragma unroll
            for (int r = 0; r < 2; r++) {
                int id = tid + 256 * r; int row = id >> 3, ch = id & 7;
                cp16(smb + (OFF_KT + (kb ^ 1) * (64 * 36) + row * 36 + ch * 4) * 4,
                     gk + (size_t)(it * 64 + 64 + row) * HH + ch * 4);
            }
        }
        CP_COMMIT();

        CP_WAIT(2); __syncthreads();           // V(it)h0 ready

        pv_half(sm, pacc, cq, ih, grp, qd, 0, pp);

        __syncthreads();                       // vh0 free
        // C3: V(it+1)h0 -> vh0
        if (it < NT - 1) {
#pragma unroll
            for (int r = 0; r < 4; r++) {
                int id = tid + 256 * r; int row = id >> 2, ch = id & 3;
                cp16(smb + (OFF_V + row * 20 + ch * 4) * 4,
                     gv + (size_t)row * (NN / 2) + jp0 + 32 + ch * 4);
            }
        }
        CP_COMMIT();
    }

    // ================= epilogue: PV(NT-1)h1 =================
    CP_WAIT(0); __syncthreads();
    pv_half(sm, pacc, cq, ih, grp, qd, 1, (NT - 1) & 1);

    // ---------------- rowsum reduce + inverse ----------------
#pragma unroll
    for (int k = 0; k < 8; k++) {
        rs[k] += __shfl_xor_sync(0xffffffffu, rs[k], 1);
        rs[k] += __shfl_xor_sync(0xffffffffu, rs[k], 2);
    }
    if (qd == 0) {
#pragma unroll
        for (int mi = 0; mi < 4; mi++) {
            sm[OFF_RS + (ei * 64 + mi * 16 + grp)     * 4 + ej] = rs[2 * mi];
            sm[OFF_RS + (ei * 64 + mi * 16 + grp + 8) * 4 + ej] = rs[2 * mi + 1];
        }
    }
    __syncthreads();
    if (tid < 128) {
        float t = sm[OFF_RS + tid * 4] + sm[OFF_RS + tid * 4 + 1]
                + sm[OFF_RS + tid * 4 + 2] + sm[OFF_RS + tid * 4 + 3];
        sm[OFF_INV + tid] = 1.0f / t;
    }
    __syncthreads();

    // ---------------- epilogue: out = acc/rowsum + x ----------------
#pragma unroll
    for (int mi = 0; mi < 4; mi++) {
        int c = cq * 64 + mi * 16 + grp;
        size_t rb0 = ((size_t)b * CC + c) * NN + i0;
        size_t rb1 = rb0 + (size_t)8 * NN;
#pragma unroll
        for (int ni = 0; ni < 8; ni++) {
            int il = ih * 64 + ni * 8 + 2 * qd;
            float iv0 = sm[OFF_INV + il];
            float iv1 = sm[OFF_INV + il + 1];
            float2 x0 = *(const float2*)(x + rb0 + il);
            float2 x1 = *(const float2*)(x + rb1 + il);
            float2 o0 = make_float2(pacc[mi][ni][0] * iv0 + x0.x,
                                    pacc[mi][ni][1] * iv1 + x0.y);
            float2 o1 = make_float2(pacc[mi][ni][2] * iv0 + x1.x,
                                    pacc[mi][ni][3] * iv1 + x1.y);
            *(float2*)(out + rb0 + il) = o0;
            *(float2*)(out + rb1 + il) = o1;
        }
    }
}

// ---------------------------------------------------------------------------
extern "C" void kernel_launch(void* const* d_in, const int* in_sizes, int n_in,
                              void* d_out, int out_size)
{
    const float* x  = (const float*)d_in[0];
    const float* wq = (const float*)d_in[1];
    const float* bq = (const float*)d_in[2];
    const float* wk = (const float*)d_in[3];
    const float* bk = (const float*)d_in[4];
    const float* wv = (const float*)d_in[5];
    const float* bv = (const float*)d_in[6];
    float* out = (float*)d_out;

    cudaFuncSetAttribute(fused_attn, cudaFuncAttributeMaxDynamicSharedMemorySize,
                         SMEM_BYTES);

    proj_kernel<<<384, 256>>>(x, wq, bq, wk, bk, wv, bv);
    fused_attn<<<dim3(NN / 128, BB), 256, SMEM_BYTES>>>(x, out);
}